// round 7
// baseline (speedup 1.0000x reference)
#include <cuda_runtime.h>
#include <math.h>

#define B_  64
#define T_  2048
#define IN_ 128
#define H_  256
#define M_  (B_ * T_)

// ---------------- scratch (static device allocations; no cudaMalloc) ----------------
__device__ float g_xp[(size_t)B_ * T_ * H_];    // reused for xp0 then xp1
__device__ float g_h1[(size_t)B_ * T_ * H_];    // layer-0 hidden states
__device__ float g_h2last[(size_t)B_ * H_];     // h2[:, T-1, :]

// ---------------- packed fp32x2 helpers (sm_103a) ----------------
__device__ __forceinline__ void fma2(unsigned long long &d, unsigned long long a, unsigned long long b) {
    asm("fma.rn.f32x2 %0, %1, %2, %0;" : "+l"(d) : "l"(a), "l"(b));
}
__device__ __forceinline__ void add2(unsigned long long &d, unsigned long long a, unsigned long long b) {
    asm("add.rn.f32x2 %0, %1, %2;" : "=l"(d) : "l"(a), "l"(b));
}
__device__ __forceinline__ unsigned long long splat2(float x) {
    unsigned long long r; asm("mov.b64 %0, {%1, %1};" : "=l"(r) : "f"(x)); return r;
}
__device__ __forceinline__ float lo2(unsigned long long v) { return __uint_as_float((unsigned)(v & 0xffffffffULL)); }
__device__ __forceinline__ float hi2(unsigned long long v) { return __uint_as_float((unsigned)(v >> 32)); }

// fast tanh: 1 - 2/(exp(2x)+1) via MUFU ex2/rcp; abs err ~5e-7, monotone, saturates
__device__ __forceinline__ float tanh_fast(float s) {
    s = fminf(fmaxf(s, -15.f), 15.f);
    float e;
    asm("ex2.approx.f32 %0, %1;" : "=f"(e) : "f"(s * 2.885390082f));
    float r;
    asm("rcp.approx.f32 %0, %1;" : "=f"(r) : "f"(e + 1.f));
    return fmaf(-2.f, r, 1.f);
}

// ---------------- cluster / mbarrier / named-barrier helpers ----------------
__device__ __forceinline__ unsigned su32(const void* p) {
    return (unsigned)__cvta_generic_to_shared(p);
}
__device__ __forceinline__ unsigned cta_rank() {
    unsigned r; asm("mov.u32 %0, %%cluster_ctarank;" : "=r"(r)); return r;
}
__device__ __forceinline__ unsigned mapa_u32(unsigned addr, unsigned rank) {
    unsigned r; asm("mapa.shared::cluster.u32 %0, %1, %2;" : "=r"(r) : "r"(addr), "r"(rank));
    return r;
}
__device__ __forceinline__ void mbar_init(unsigned addr, unsigned cnt) {
    asm volatile("mbarrier.init.shared.b64 [%0], %1;" :: "r"(addr), "r"(cnt) : "memory");
}
__device__ __forceinline__ void mbar_expect_tx(unsigned addr, unsigned bytes) {
    asm volatile("mbarrier.arrive.expect_tx.shared.b64 _, [%0], %1;" :: "r"(addr), "r"(bytes) : "memory");
}
__device__ __forceinline__ void mbar_wait_cluster(unsigned addr, unsigned parity) {
    asm volatile(
        "{\n\t.reg .pred P;\n\t"
        "WL_%=:\n\t"
        "mbarrier.try_wait.parity.acquire.cluster.shared::cta.b64 P, [%0], %1, 0x989680;\n\t"
        "@P bra.uni WD_%=;\n\t"
        "bra.uni WL_%=;\n\t"
        "WD_%=:\n\t}"
        :: "r"(addr), "r"(parity) : "memory");
}
__device__ __forceinline__ void st_async_f32(unsigned remote_addr, float v, unsigned remote_mbar) {
    asm volatile(
        "st.async.shared::cluster.mbarrier::complete_tx::bytes.b32 [%0], %1, [%2];"
        :: "r"(remote_addr), "r"(__float_as_uint(v)), "r"(remote_mbar) : "memory");
}
__device__ __forceinline__ void cluster_sync_() {
    asm volatile("barrier.cluster.arrive.aligned;" ::: "memory");
    asm volatile("barrier.cluster.wait.aligned;" ::: "memory");
}
__device__ __forceinline__ void bar_sync(int id, int cnt) {
    asm volatile("bar.sync %0, %1;" :: "r"(id), "r"(cnt) : "memory");
}
__device__ __forceinline__ void bar_arrive(int id, int cnt) {
    asm volatile("bar.arrive %0, %1;" :: "r"(id), "r"(cnt) : "memory");
}

// =====================================================================================
// Phase A / C: C[m][n] = sum_k A[m][k] * W[n][k] + bias0[n] + bias1[n]
// =====================================================================================
__global__ __launch_bounds__(256, 2)
void gemm_bias_kernel(const float* __restrict__ A, const float* __restrict__ W,
                      const float* __restrict__ bias0, const float* __restrict__ bias1,
                      float* __restrict__ C, int K)
{
    __shared__ float a_sm[16][132];
    __shared__ float b_sm[16][132];

    const int tid = threadIdx.x;
    const int tx = tid & 15, ty = tid >> 4;
    const int mBase = blockIdx.x * 128;
    const int nBase = blockIdx.y * 128;

    unsigned long long acc[8][4];
#pragma unroll
    for (int i = 0; i < 8; i++)
#pragma unroll
        for (int j = 0; j < 4; j++) acc[i][j] = 0ULL;

    for (int kt = 0; kt < K; kt += 16) {
#pragma unroll
        for (int l = 0; l < 2; l++) {
            int idx = l * 256 + tid;
            int row = idx >> 2, kq = idx & 3;
            float4 v = *(const float4*)(A + (size_t)(mBase + row) * K + kt + kq * 4);
            a_sm[kq * 4 + 0][row] = v.x; a_sm[kq * 4 + 1][row] = v.y;
            a_sm[kq * 4 + 2][row] = v.z; a_sm[kq * 4 + 3][row] = v.w;
        }
#pragma unroll
        for (int l = 0; l < 2; l++) {
            int idx = l * 256 + tid;
            int row = idx >> 2, kq = idx & 3;
            float4 v = *(const float4*)(W + (size_t)(nBase + row) * K + kt + kq * 4);
            b_sm[kq * 4 + 0][row] = v.x; b_sm[kq * 4 + 1][row] = v.y;
            b_sm[kq * 4 + 2][row] = v.z; b_sm[kq * 4 + 3][row] = v.w;
        }
        __syncthreads();

#pragma unroll
        for (int kk = 0; kk < 16; kk++) {
            float4 a0 = *(const float4*)&a_sm[kk][ty * 8];
            float4 a1 = *(const float4*)&a_sm[kk][ty * 8 + 4];
            ulonglong2 b0 = *(const ulonglong2*)&b_sm[kk][tx * 8];
            ulonglong2 b1 = *(const ulonglong2*)&b_sm[kk][tx * 8 + 4];
            float av[8] = {a0.x, a0.y, a0.z, a0.w, a1.x, a1.y, a1.z, a1.w};
#pragma unroll
            for (int i = 0; i < 8; i++) {
                unsigned long long s = splat2(av[i]);
                fma2(acc[i][0], s, b0.x);
                fma2(acc[i][1], s, b0.y);
                fma2(acc[i][2], s, b1.x);
                fma2(acc[i][3], s, b1.y);
            }
        }
        __syncthreads();
    }

    const int n0 = nBase + tx * 8;
    float bj[8];
#pragma unroll
    for (int j = 0; j < 8; j++) bj[j] = bias0[n0 + j] + bias1[n0 + j];

#pragma unroll
    for (int i = 0; i < 8; i++) {
        int m = mBase + ty * 8 + i;
        float4 o0, o1;
        o0.x = lo2(acc[i][0]) + bj[0]; o0.y = hi2(acc[i][0]) + bj[1];
        o0.z = lo2(acc[i][1]) + bj[2]; o0.w = hi2(acc[i][1]) + bj[3];
        o1.x = lo2(acc[i][2]) + bj[4]; o1.y = hi2(acc[i][2]) + bj[5];
        o1.z = lo2(acc[i][3]) + bj[6]; o1.w = hi2(acc[i][3]) + bj[7];
        *(float4*)(C + (size_t)m * H_ + n0)     = o0;
        *(float4*)(C + (size_t)m * H_ + n0 + 4) = o1;
    }
}

// =====================================================================================
// Recurrence v5 (decoupled roles): 64 clusters x 2 CTAs, 1 batch row/cluster.
// Data plan = rec4 partial-sum exchange:  y[o] = W[o, own 128 k] @ h_own[t-1].
// Role plan (NEW):
//   SENDERS  = warps 4-7 (hi-wid -> arbiter priority; they're the critical path):
//     bar.sync(1,256)  [h_own[t-1] ready]  -> arm mbar phase t+1 -> matvec ->
//     st.async partials for the peer's 128 outputs (phase t).
//   RECEIVERS = warps 0-3:
//     matvec own-output partials (pre-wait; fills the flight shadow) ->
//     mbar wait(phase t) -> combine + xp + tanh -> STS h_own[t] -> bar.arrive(1,256)
//     -> optional STG -> bar.sync(2,128) [receiver group only].
// Receivers never wait on senders; senders wait only for h_own[t-1].
// Double buffers h_sm / p_rcv; mbar[t&1], parity (t>>1)&1, expect_tx 512B/phase.
// =====================================================================================
template<bool STORE_ALL>
__global__ void __cluster_dims__(2, 1, 1) __launch_bounds__(256, 1)
rnn_rec5(const float* __restrict__ xp, const float* __restrict__ Whh,
         float* __restrict__ hout)
{
    __shared__ __align__(16) float h_sm[2][132];    // own h chunk (double buffered)
    __shared__ __align__(16) float p_rcv[2][128];   // incoming peer partials
    __shared__ __align__(8)  unsigned long long mbar[2];

    const int tid = threadIdx.x;
    const unsigned rank = cta_rank();              // 0 or 1
    const unsigned peer = rank ^ 1u;
    const int b = blockIdx.x >> 1;                 // batch row
    const int is_send = tid >> 7;                  // warps 4-7 send (hi priority)
    const int oi = tid & 127;
    const int o_glob = (is_send ? (int)peer : (int)rank) * 128 + oi;

    // ---- W slice: Whh[o_glob][rank*128 .. +128) as 32 ulonglong2 (128 floats) ----
    unsigned long long wq[64];
    {
        const ulonglong2* src = (const ulonglong2*)(Whh + (size_t)o_glob * H_ + (int)rank * 128);
#pragma unroll
        for (int j = 0; j < 32; ++j) { ulonglong2 v = src[j]; wq[2 * j] = v.x; wq[2 * j + 1] = v.y; }
    }

    // ---- init ----
    if (tid == 0) { mbar_init(su32(&mbar[0]), 1); mbar_init(su32(&mbar[1]), 1); }
    for (int i = tid; i < 2 * 132; i += 256) ((float*)h_sm)[i] = 0.f;   // h[-1] = 0
    __syncthreads();
    cluster_sync_();                                // peer mbars live
    if (tid == 128) mbar_expect_tx(su32(&mbar[0]), 512u);   // arm phase 0
    cluster_sync_();                                // both CTAs armed before any send

    const unsigned my_mbar   = su32(&mbar[0]);
    const unsigned peer_mbar = mapa_u32(my_mbar, peer);
    const unsigned peer_prcv = mapa_u32(su32(&p_rcv[0][0]), peer);

    if (is_send) {
        // =================== SENDER warps (4-7) ===================
        for (int t = 0; t < T_; ++t) {
            const int cb = t & 1;
            bar_sync(1, 256);                                       // h_own[t-1] ready
            if (tid == 128)
                mbar_expect_tx(my_mbar + (unsigned)((t + 1) & 1) * 8u, 512u);  // arm t+1

            const float* hb = &h_sm[cb][0];
            unsigned long long a0 = 0, a1 = 0, a2 = 0, a3 = 0;
#pragma unroll
            for (int kk = 0; kk < 32; kk += 2) {
                ulonglong2 v0 = *(const ulonglong2*)(hb + kk * 4);
                ulonglong2 v1 = *(const ulonglong2*)(hb + kk * 4 + 4);
                fma2(a0, v0.x, wq[2 * kk]);
                fma2(a1, v0.y, wq[2 * kk + 1]);
                fma2(a2, v1.x, wq[2 * kk + 2]);
                fma2(a3, v1.y, wq[2 * kk + 3]);
            }
            unsigned long long s01, s23, s;
            add2(s01, a0, a1); add2(s23, a2, a3); add2(s, s01, s23);
            float p = lo2(s) + hi2(s);

            st_async_f32(peer_prcv + (unsigned)(cb * 128 + oi) * 4u,
                         p, peer_mbar + (unsigned)cb * 8u);          // ship phase t
        }
    } else {
        // =================== RECEIVER warps (0-3) ===================
        bar_arrive(1, 256);                         // prime: h[-1] already in smem
        const size_t xrow = ((size_t)b * T_) * H_ + o_glob;
        float xv = __ldg(xp + xrow);

        for (int t = 0; t < T_; ++t) {
            const int cb = t & 1, nb = cb ^ 1;

            float xvn = 0.f;
            if (t + 1 < T_) xvn = __ldg(xp + xrow + (size_t)(t + 1) * H_);

            // own-output partials over own k-half (no peer dependency)
            const float* hb = &h_sm[cb][0];
            unsigned long long a0 = 0, a1 = 0, a2 = 0, a3 = 0;
#pragma unroll
            for (int kk = 0; kk < 32; kk += 2) {
                ulonglong2 v0 = *(const ulonglong2*)(hb + kk * 4);
                ulonglong2 v1 = *(const ulonglong2*)(hb + kk * 4 + 4);
                fma2(a0, v0.x, wq[2 * kk]);
                fma2(a1, v0.y, wq[2 * kk + 1]);
                fma2(a2, v1.x, wq[2 * kk + 2]);
                fma2(a3, v1.y, wq[2 * kk + 3]);
            }
            unsigned long long s01, s23, s;
            add2(s01, a0, a1); add2(s23, a2, a3); add2(s, s01, s23);
            float p = lo2(s) + hi2(s);

            // wait for peer partials of THIS step (maximally late)
            mbar_wait_cluster(my_mbar + (unsigned)cb * 8u, (unsigned)(t >> 1) & 1u);
            float h = tanh_fast(xv + p + p_rcv[cb][oi]);
            h_sm[nb][oi] = h;                        // h_own[t] for step t+1
            bar_arrive(1, 256);                      // release senders for t+1

            if (STORE_ALL)
                hout[((size_t)b * T_ + t) * H_ + o_glob] = h;
            else if (t == T_ - 1)
                hout[(size_t)b * H_ + o_glob] = h;

            bar_sync(2, 128);                        // receiver group: STS visible
            xv = xvn;
        }
    }
    cluster_sync_();   // all phases consumed on both sides before exit
}

// =====================================================================================
// Final FC: out[b] = dot(h2last[b, :], W_fc[0,:]) + b_fc[0]
// =====================================================================================
__global__ void fc_kernel(const float* __restrict__ h2l, const float* __restrict__ Wfc,
                          const float* __restrict__ bfc, float* __restrict__ out)
{
    __shared__ float red[8];
    int b = blockIdx.x, tid = threadIdx.x;
    float v = h2l[(size_t)b * H_ + tid] * Wfc[tid];
#pragma unroll
    for (int o = 16; o > 0; o >>= 1) v += __shfl_down_sync(0xffffffffu, v, o);
    if ((tid & 31) == 0) red[tid >> 5] = v;
    __syncthreads();
    if (tid < 8) {
        float s = red[tid];
#pragma unroll
        for (int o = 4; o > 0; o >>= 1) s += __shfl_down_sync(0xffu, s, o);
        if (tid == 0) out[b] = s + bfc[0];
    }
}

// =====================================================================================
extern "C" void kernel_launch(void* const* d_in, const int* in_sizes, int n_in,
                              void* d_out, int out_size)
{
    const float* x     = (const float*)d_in[0];
    const float* W_ih0 = (const float*)d_in[1];
    const float* W_hh0 = (const float*)d_in[2];
    const float* b_ih0 = (const float*)d_in[3];
    const float* b_hh0 = (const float*)d_in[4];
    const float* W_ih1 = (const float*)d_in[5];
    const float* W_hh1 = (const float*)d_in[6];
    const float* b_ih1 = (const float*)d_in[7];
    const float* b_hh1 = (const float*)d_in[8];
    const float* W_fc  = (const float*)d_in[9];
    const float* b_fc  = (const float*)d_in[10];
    float* out = (float*)d_out;

    float *xp, *h1, *h2l;
    cudaGetSymbolAddress((void**)&xp, g_xp);
    cudaGetSymbolAddress((void**)&h1, g_h1);
    cudaGetSymbolAddress((void**)&h2l, g_h2last);

    dim3 ggemm(M_ / 128, H_ / 128);

    // Phase A: xp0 = x @ W_ih0^T + b_ih0 + b_hh0
    gemm_bias_kernel<<<ggemm, 256>>>(x, W_ih0, b_ih0, b_hh0, xp, IN_);
    // Phase B: layer-0 recurrence -> h1 (streams all steps)
    rnn_rec5<true><<<128, 256>>>(xp, W_hh0, h1);
    // Phase C: xp1 = h1 @ W_ih1^T + b_ih1 + b_hh1
    gemm_bias_kernel<<<ggemm, 256>>>(h1, W_ih1, b_ih1, b_hh1, xp, H_);
    // Phase D: layer-1 recurrence -> only h2[T-1]
    rnn_rec5<false><<<128, 256>>>(xp, W_hh1, h2l);
    // Phase E: final projection
    fc_kernel<<<B_, H_>>>(h2l, W_fc, b_fc, out);
}

// round 8
// speedup vs baseline: 1.0003x; 1.0003x over previous
#include <cuda_runtime.h>
#include <math.h>

#define B_  64
#define T_  2048
#define IN_ 128
#define H_  256
#define M_  (B_ * T_)

// ---------------- scratch (static device allocations; no cudaMalloc) ----------------
__device__ float g_xp[(size_t)B_ * T_ * H_];    // reused for xp0 then xp1
__device__ float g_h1[(size_t)B_ * T_ * H_];    // layer-0 hidden states
__device__ float g_h2last[(size_t)B_ * H_];     // h2[:, T-1, :]

// ---------------- packed fp32x2 helpers (sm_103a) ----------------
__device__ __forceinline__ void fma2(unsigned long long &d, unsigned long long a, unsigned long long b) {
    asm("fma.rn.f32x2 %0, %1, %2, %0;" : "+l"(d) : "l"(a), "l"(b));
}
__device__ __forceinline__ void add2(unsigned long long &d, unsigned long long a, unsigned long long b) {
    asm("add.rn.f32x2 %0, %1, %2;" : "=l"(d) : "l"(a), "l"(b));
}
__device__ __forceinline__ unsigned long long splat2(float x) {
    unsigned long long r; asm("mov.b64 %0, {%1, %1};" : "=l"(r) : "f"(x)); return r;
}
__device__ __forceinline__ float lo2(unsigned long long v) { return __uint_as_float((unsigned)(v & 0xffffffffULL)); }
__device__ __forceinline__ float hi2(unsigned long long v) { return __uint_as_float((unsigned)(v >> 32)); }

// fast tanh: 1 - 2/(exp(2x)+1) via MUFU ex2/rcp; abs err ~5e-7, monotone, saturates
__device__ __forceinline__ float tanh_fast(float s) {
    s = fminf(fmaxf(s, -15.f), 15.f);
    float e;
    asm("ex2.approx.f32 %0, %1;" : "=f"(e) : "f"(s * 2.885390082f));
    float r;
    asm("rcp.approx.f32 %0, %1;" : "=f"(r) : "f"(e + 1.f));
    return fmaf(-2.f, r, 1.f);
}

// ---------------- cluster / mbarrier / named-barrier helpers ----------------
__device__ __forceinline__ unsigned su32(const void* p) {
    return (unsigned)__cvta_generic_to_shared(p);
}
__device__ __forceinline__ unsigned cta_rank() {
    unsigned r; asm("mov.u32 %0, %%cluster_ctarank;" : "=r"(r)); return r;
}
__device__ __forceinline__ unsigned mapa_u32(unsigned addr, unsigned rank) {
    unsigned r; asm("mapa.shared::cluster.u32 %0, %1, %2;" : "=r"(r) : "r"(addr), "r"(rank));
    return r;
}
__device__ __forceinline__ void mbar_init(unsigned addr, unsigned cnt) {
    asm volatile("mbarrier.init.shared.b64 [%0], %1;" :: "r"(addr), "r"(cnt) : "memory");
}
__device__ __forceinline__ void mbar_expect_tx(unsigned addr, unsigned bytes) {
    asm volatile("mbarrier.arrive.expect_tx.shared.b64 _, [%0], %1;" :: "r"(addr), "r"(bytes) : "memory");
}
__device__ __forceinline__ void mbar_wait_cluster(unsigned addr, unsigned parity) {
    asm volatile(
        "{\n\t.reg .pred P;\n\t"
        "WL_%=:\n\t"
        "mbarrier.try_wait.parity.acquire.cluster.shared::cta.b64 P, [%0], %1, 0x989680;\n\t"
        "@P bra.uni WD_%=;\n\t"
        "bra.uni WL_%=;\n\t"
        "WD_%=:\n\t}"
        :: "r"(addr), "r"(parity) : "memory");
}
__device__ __forceinline__ void st_async_f32(unsigned remote_addr, float v, unsigned remote_mbar) {
    asm volatile(
        "st.async.shared::cluster.mbarrier::complete_tx::bytes.b32 [%0], %1, [%2];"
        :: "r"(remote_addr), "r"(__float_as_uint(v)), "r"(remote_mbar) : "memory");
}
__device__ __forceinline__ void cluster_sync_() {
    asm volatile("barrier.cluster.arrive.aligned;" ::: "memory");
    asm volatile("barrier.cluster.wait.aligned;" ::: "memory");
}
__device__ __forceinline__ void bar_sync(int id, int cnt) {
    asm volatile("bar.sync %0, %1;" :: "r"(id), "r"(cnt) : "memory");
}
__device__ __forceinline__ void bar_arrive(int id, int cnt) {
    asm volatile("bar.arrive %0, %1;" :: "r"(id), "r"(cnt) : "memory");
}

// =====================================================================================
// Phase A / C: C[m][n] = sum_k A[m][k] * W[n][k] + bias0[n] + bias1[n]
// =====================================================================================
__global__ __launch_bounds__(256, 2)
void gemm_bias_kernel(const float* __restrict__ A, const float* __restrict__ W,
                      const float* __restrict__ bias0, const float* __restrict__ bias1,
                      float* __restrict__ C, int K)
{
    __shared__ float a_sm[16][132];
    __shared__ float b_sm[16][132];

    const int tid = threadIdx.x;
    const int tx = tid & 15, ty = tid >> 4;
    const int mBase = blockIdx.x * 128;
    const int nBase = blockIdx.y * 128;

    unsigned long long acc[8][4];
#pragma unroll
    for (int i = 0; i < 8; i++)
#pragma unroll
        for (int j = 0; j < 4; j++) acc[i][j] = 0ULL;

    for (int kt = 0; kt < K; kt += 16) {
#pragma unroll
        for (int l = 0; l < 2; l++) {
            int idx = l * 256 + tid;
            int row = idx >> 2, kq = idx & 3;
            float4 v = *(const float4*)(A + (size_t)(mBase + row) * K + kt + kq * 4);
            a_sm[kq * 4 + 0][row] = v.x; a_sm[kq * 4 + 1][row] = v.y;
            a_sm[kq * 4 + 2][row] = v.z; a_sm[kq * 4 + 3][row] = v.w;
        }
#pragma unroll
        for (int l = 0; l < 2; l++) {
            int idx = l * 256 + tid;
            int row = idx >> 2, kq = idx & 3;
            float4 v = *(const float4*)(W + (size_t)(nBase + row) * K + kt + kq * 4);
            b_sm[kq * 4 + 0][row] = v.x; b_sm[kq * 4 + 1][row] = v.y;
            b_sm[kq * 4 + 2][row] = v.z; b_sm[kq * 4 + 3][row] = v.w;
        }
        __syncthreads();

#pragma unroll
        for (int kk = 0; kk < 16; kk++) {
            float4 a0 = *(const float4*)&a_sm[kk][ty * 8];
            float4 a1 = *(const float4*)&a_sm[kk][ty * 8 + 4];
            ulonglong2 b0 = *(const ulonglong2*)&b_sm[kk][tx * 8];
            ulonglong2 b1 = *(const ulonglong2*)&b_sm[kk][tx * 8 + 4];
            float av[8] = {a0.x, a0.y, a0.z, a0.w, a1.x, a1.y, a1.z, a1.w};
#pragma unroll
            for (int i = 0; i < 8; i++) {
                unsigned long long s = splat2(av[i]);
                fma2(acc[i][0], s, b0.x);
                fma2(acc[i][1], s, b0.y);
                fma2(acc[i][2], s, b1.x);
                fma2(acc[i][3], s, b1.y);
            }
        }
        __syncthreads();
    }

    const int n0 = nBase + tx * 8;
    float bj[8];
#pragma unroll
    for (int j = 0; j < 8; j++) bj[j] = bias0[n0 + j] + bias1[n0 + j];

#pragma unroll
    for (int i = 0; i < 8; i++) {
        int m = mBase + ty * 8 + i;
        float4 o0, o1;
        o0.x = lo2(acc[i][0]) + bj[0]; o0.y = hi2(acc[i][0]) + bj[1];
        o0.z = lo2(acc[i][1]) + bj[2]; o0.w = hi2(acc[i][1]) + bj[3];
        o1.x = lo2(acc[i][2]) + bj[4]; o1.y = hi2(acc[i][2]) + bj[5];
        o1.z = lo2(acc[i][3]) + bj[6]; o1.w = hi2(acc[i][3]) + bj[7];
        *(float4*)(C + (size_t)m * H_ + n0)     = o0;
        *(float4*)(C + (size_t)m * H_ + n0 + 4) = o1;
    }
}

// =====================================================================================
// Recurrence v5 (decoupled roles): 64 clusters x 2 CTAs, 1 batch row/cluster.
// Data plan = rec4 partial-sum exchange:  y[o] = W[o, own 128 k] @ h_own[t-1].
// Role plan (NEW):
//   SENDERS  = warps 4-7 (hi-wid -> arbiter priority; they're the critical path):
//     bar.sync(1,256)  [h_own[t-1] ready]  -> arm mbar phase t+1 -> matvec ->
//     st.async partials for the peer's 128 outputs (phase t).
//   RECEIVERS = warps 0-3:
//     matvec own-output partials (pre-wait; fills the flight shadow) ->
//     mbar wait(phase t) -> combine + xp + tanh -> STS h_own[t] -> bar.arrive(1,256)
//     -> optional STG -> bar.sync(2,128) [receiver group only].
// Receivers never wait on senders; senders wait only for h_own[t-1].
// Double buffers h_sm / p_rcv; mbar[t&1], parity (t>>1)&1, expect_tx 512B/phase.
// =====================================================================================
template<bool STORE_ALL>
__global__ void __cluster_dims__(2, 1, 1) __launch_bounds__(256, 1)
rnn_rec5(const float* __restrict__ xp, const float* __restrict__ Whh,
         float* __restrict__ hout)
{
    __shared__ __align__(16) float h_sm[2][132];    // own h chunk (double buffered)
    __shared__ __align__(16) float p_rcv[2][128];   // incoming peer partials
    __shared__ __align__(8)  unsigned long long mbar[2];

    const int tid = threadIdx.x;
    const unsigned rank = cta_rank();              // 0 or 1
    const unsigned peer = rank ^ 1u;
    const int b = blockIdx.x >> 1;                 // batch row
    const int is_send = tid >> 7;                  // warps 4-7 send (hi priority)
    const int oi = tid & 127;
    const int o_glob = (is_send ? (int)peer : (int)rank) * 128 + oi;

    // ---- W slice: Whh[o_glob][rank*128 .. +128) as 32 ulonglong2 (128 floats) ----
    unsigned long long wq[64];
    {
        const ulonglong2* src = (const ulonglong2*)(Whh + (size_t)o_glob * H_ + (int)rank * 128);
#pragma unroll
        for (int j = 0; j < 32; ++j) { ulonglong2 v = src[j]; wq[2 * j] = v.x; wq[2 * j + 1] = v.y; }
    }

    // ---- init ----
    if (tid == 0) { mbar_init(su32(&mbar[0]), 1); mbar_init(su32(&mbar[1]), 1); }
    for (int i = tid; i < 2 * 132; i += 256) ((float*)h_sm)[i] = 0.f;   // h[-1] = 0
    __syncthreads();
    cluster_sync_();                                // peer mbars live
    if (tid == 128) mbar_expect_tx(su32(&mbar[0]), 512u);   // arm phase 0
    cluster_sync_();                                // both CTAs armed before any send

    const unsigned my_mbar   = su32(&mbar[0]);
    const unsigned peer_mbar = mapa_u32(my_mbar, peer);
    const unsigned peer_prcv = mapa_u32(su32(&p_rcv[0][0]), peer);

    if (is_send) {
        // =================== SENDER warps (4-7) ===================
        for (int t = 0; t < T_; ++t) {
            const int cb = t & 1;
            bar_sync(1, 256);                                       // h_own[t-1] ready
            if (tid == 128)
                mbar_expect_tx(my_mbar + (unsigned)((t + 1) & 1) * 8u, 512u);  // arm t+1

            const float* hb = &h_sm[cb][0];
            unsigned long long a0 = 0, a1 = 0, a2 = 0, a3 = 0;
#pragma unroll
            for (int kk = 0; kk < 32; kk += 2) {
                ulonglong2 v0 = *(const ulonglong2*)(hb + kk * 4);
                ulonglong2 v1 = *(const ulonglong2*)(hb + kk * 4 + 4);
                fma2(a0, v0.x, wq[2 * kk]);
                fma2(a1, v0.y, wq[2 * kk + 1]);
                fma2(a2, v1.x, wq[2 * kk + 2]);
                fma2(a3, v1.y, wq[2 * kk + 3]);
            }
            unsigned long long s01, s23, s;
            add2(s01, a0, a1); add2(s23, a2, a3); add2(s, s01, s23);
            float p = lo2(s) + hi2(s);

            st_async_f32(peer_prcv + (unsigned)(cb * 128 + oi) * 4u,
                         p, peer_mbar + (unsigned)cb * 8u);          // ship phase t
        }
    } else {
        // =================== RECEIVER warps (0-3) ===================
        bar_arrive(1, 256);                         // prime: h[-1] already in smem
        const size_t xrow = ((size_t)b * T_) * H_ + o_glob;
        float xv = __ldg(xp + xrow);

        for (int t = 0; t < T_; ++t) {
            const int cb = t & 1, nb = cb ^ 1;

            float xvn = 0.f;
            if (t + 1 < T_) xvn = __ldg(xp + xrow + (size_t)(t + 1) * H_);

            // own-output partials over own k-half (no peer dependency)
            const float* hb = &h_sm[cb][0];
            unsigned long long a0 = 0, a1 = 0, a2 = 0, a3 = 0;
#pragma unroll
            for (int kk = 0; kk < 32; kk += 2) {
                ulonglong2 v0 = *(const ulonglong2*)(hb + kk * 4);
                ulonglong2 v1 = *(const ulonglong2*)(hb + kk * 4 + 4);
                fma2(a0, v0.x, wq[2 * kk]);
                fma2(a1, v0.y, wq[2 * kk + 1]);
                fma2(a2, v1.x, wq[2 * kk + 2]);
                fma2(a3, v1.y, wq[2 * kk + 3]);
            }
            unsigned long long s01, s23, s;
            add2(s01, a0, a1); add2(s23, a2, a3); add2(s, s01, s23);
            float p = lo2(s) + hi2(s);

            // wait for peer partials of THIS step (maximally late)
            mbar_wait_cluster(my_mbar + (unsigned)cb * 8u, (unsigned)(t >> 1) & 1u);
            float h = tanh_fast(xv + p + p_rcv[cb][oi]);
            h_sm[nb][oi] = h;                        // h_own[t] for step t+1
            bar_arrive(1, 256);                      // release senders for t+1

            if (STORE_ALL)
                hout[((size_t)b * T_ + t) * H_ + o_glob] = h;
            else if (t == T_ - 1)
                hout[(size_t)b * H_ + o_glob] = h;

            bar_sync(2, 128);                        // receiver group: STS visible
            xv = xvn;
        }
    }
    cluster_sync_();   // all phases consumed on both sides before exit
}

// =====================================================================================
// Final FC: out[b] = dot(h2last[b, :], W_fc[0,:]) + b_fc[0]
// =====================================================================================
__global__ void fc_kernel(const float* __restrict__ h2l, const float* __restrict__ Wfc,
                          const float* __restrict__ bfc, float* __restrict__ out)
{
    __shared__ float red[8];
    int b = blockIdx.x, tid = threadIdx.x;
    float v = h2l[(size_t)b * H_ + tid] * Wfc[tid];
#pragma unroll
    for (int o = 16; o > 0; o >>= 1) v += __shfl_down_sync(0xffffffffu, v, o);
    if ((tid & 31) == 0) red[tid >> 5] = v;
    __syncthreads();
    if (tid < 8) {
        float s = red[tid];
#pragma unroll
        for (int o = 4; o > 0; o >>= 1) s += __shfl_down_sync(0xffu, s, o);
        if (tid == 0) out[b] = s + bfc[0];
    }
}

// =====================================================================================
extern "C" void kernel_launch(void* const* d_in, const int* in_sizes, int n_in,
                              void* d_out, int out_size)
{
    const float* x     = (const float*)d_in[0];
    const float* W_ih0 = (const float*)d_in[1];
    const float* W_hh0 = (const float*)d_in[2];
    const float* b_ih0 = (const float*)d_in[3];
    const float* b_hh0 = (const float*)d_in[4];
    const float* W_ih1 = (const float*)d_in[5];
    const float* W_hh1 = (const float*)d_in[6];
    const float* b_ih1 = (const float*)d_in[7];
    const float* b_hh1 = (const float*)d_in[8];
    const float* W_fc  = (const float*)d_in[9];
    const float* b_fc  = (const float*)d_in[10];
    float* out = (float*)d_out;

    float *xp, *h1, *h2l;
    cudaGetSymbolAddress((void**)&xp, g_xp);
    cudaGetSymbolAddress((void**)&h1, g_h1);
    cudaGetSymbolAddress((void**)&h2l, g_h2last);

    dim3 ggemm(M_ / 128, H_ / 128);

    // Phase A: xp0 = x @ W_ih0^T + b_ih0 + b_hh0
    gemm_bias_kernel<<<ggemm, 256>>>(x, W_ih0, b_ih0, b_hh0, xp, IN_);
    // Phase B: layer-0 recurrence -> h1 (streams all steps)
    rnn_rec5<true><<<128, 256>>>(xp, W_hh0, h1);
    // Phase C: xp1 = h1 @ W_ih1^T + b_ih1 + b_hh1
    gemm_bias_kernel<<<ggemm, 256>>>(h1, W_ih1, b_ih1, b_hh1, xp, H_);
    // Phase D: layer-1 recurrence -> only h2[T-1]
    rnn_rec5<false><<<128, 256>>>(xp, W_hh1, h2l);
    // Phase E: final projection
    fc_kernel<<<B_, H_>>>(h2l, W_fc, b_fc, out);
}

// round 9
// speedup vs baseline: 1.1386x; 1.1383x over previous
#include <cuda_runtime.h>
#include <math.h>

#define B_  64
#define T_  2048
#define IN_ 128
#define H_  256
#define M_  (B_ * T_)

// ---------------- scratch ----------------
__device__ float g_xp[(size_t)B_ * T_ * H_];    // xp0
__device__ float g_h2last[(size_t)B_ * H_];     // h2[:, T-1, :]

typedef unsigned long long ull;

// ---------------- packed fp32x2 helpers ----------------
__device__ __forceinline__ void fma2(ull &d, ull a, ull b) {
    asm("fma.rn.f32x2 %0, %1, %2, %0;" : "+l"(d) : "l"(a), "l"(b));
}
__device__ __forceinline__ void add2(ull &d, ull a, ull b) {
    asm("add.rn.f32x2 %0, %1, %2;" : "=l"(d) : "l"(a), "l"(b));
}
__device__ __forceinline__ ull splat2(float x) {
    ull r; asm("mov.b64 %0, {%1, %1};" : "=l"(r) : "f"(x)); return r;
}
__device__ __forceinline__ ull pack2(float a, float b) {
    ull r; asm("mov.b64 %0, {%1, %2};" : "=l"(r) : "r"(__float_as_uint(a)), "r"(__float_as_uint(b)));
    return r;
}
__device__ __forceinline__ float lo2(ull v) { return __uint_as_float((unsigned)(v & 0xffffffffULL)); }
__device__ __forceinline__ float hi2(ull v) { return __uint_as_float((unsigned)(v >> 32)); }

__device__ __forceinline__ float tanh_fast(float s) {
    s = fminf(fmaxf(s, -15.f), 15.f);
    float e; asm("ex2.approx.f32 %0, %1;" : "=f"(e) : "f"(s * 2.885390082f));
    float r; asm("rcp.approx.f32 %0, %1;" : "=f"(r) : "f"(e + 1.f));
    return fmaf(-2.f, r, 1.f);
}

// ---------------- cluster / mbarrier helpers ----------------
__device__ __forceinline__ unsigned su32(const void* p) {
    return (unsigned)__cvta_generic_to_shared(p);
}
__device__ __forceinline__ unsigned cta_rank() {
    unsigned r; asm("mov.u32 %0, %%cluster_ctarank;" : "=r"(r)); return r;
}
__device__ __forceinline__ unsigned mapa_u32(unsigned addr, unsigned rank) {
    unsigned r; asm("mapa.shared::cluster.u32 %0, %1, %2;" : "=r"(r) : "r"(addr), "r"(rank));
    return r;
}
__device__ __forceinline__ void mbar_init(unsigned addr, unsigned cnt) {
    asm volatile("mbarrier.init.shared.b64 [%0], %1;" :: "r"(addr), "r"(cnt) : "memory");
}
__device__ __forceinline__ void mbar_expect_tx(unsigned addr, unsigned bytes) {
    asm volatile("mbarrier.arrive.expect_tx.shared.b64 _, [%0], %1;" :: "r"(addr), "r"(bytes) : "memory");
}
__device__ __forceinline__ void mbar_arrive_local(unsigned addr) {
    asm volatile("mbarrier.arrive.release.cta.shared.b64 _, [%0];" :: "r"(addr) : "memory");
}
__device__ __forceinline__ void mbar_wait_cluster(unsigned addr, unsigned parity) {
    asm volatile(
        "{\n\t.reg .pred P;\n\t"
        "WL_%=:\n\t"
        "mbarrier.try_wait.parity.acquire.cluster.shared::cta.b64 P, [%0], %1, 0x989680;\n\t"
        "@P bra.uni WD_%=;\n\t"
        "bra.uni WL_%=;\n\t"
        "WD_%=:\n\t}"
        :: "r"(addr), "r"(parity) : "memory");
}
__device__ __forceinline__ void st_async_b64(unsigned raddr, ull v, unsigned rmbar) {
    asm volatile(
        "st.async.shared::cluster.mbarrier::complete_tx::bytes.b64 [%0], %1, [%2];"
        :: "r"(raddr), "l"(v), "r"(rmbar) : "memory");
}
__device__ __forceinline__ void cluster_sync_() {
    asm volatile("barrier.cluster.arrive.aligned;" ::: "memory");
    asm volatile("barrier.cluster.wait.aligned;" ::: "memory");
}

// =====================================================================================
// Phase A: xp0[m][n] = sum_k x[m][k] * W_ih0[n][k] + b_ih0[n] + b_hh0[n]
// =====================================================================================
__global__ __launch_bounds__(256, 2)
void gemm_bias_kernel(const float* __restrict__ A, const float* __restrict__ W,
                      const float* __restrict__ bias0, const float* __restrict__ bias1,
                      float* __restrict__ C, int K)
{
    __shared__ float a_sm[16][132];
    __shared__ float b_sm[16][132];

    const int tid = threadIdx.x;
    const int tx = tid & 15, ty = tid >> 4;
    const int mBase = blockIdx.x * 128;
    const int nBase = blockIdx.y * 128;

    ull acc[8][4];
#pragma unroll
    for (int i = 0; i < 8; i++)
#pragma unroll
        for (int j = 0; j < 4; j++) acc[i][j] = 0ULL;

    for (int kt = 0; kt < K; kt += 16) {
#pragma unroll
        for (int l = 0; l < 2; l++) {
            int idx = l * 256 + tid;
            int row = idx >> 2, kq = idx & 3;
            float4 v = *(const float4*)(A + (size_t)(mBase + row) * K + kt + kq * 4);
            a_sm[kq * 4 + 0][row] = v.x; a_sm[kq * 4 + 1][row] = v.y;
            a_sm[kq * 4 + 2][row] = v.z; a_sm[kq * 4 + 3][row] = v.w;
        }
#pragma unroll
        for (int l = 0; l < 2; l++) {
            int idx = l * 256 + tid;
            int row = idx >> 2, kq = idx & 3;
            float4 v = *(const float4*)(W + (size_t)(nBase + row) * K + kt + kq * 4);
            b_sm[kq * 4 + 0][row] = v.x; b_sm[kq * 4 + 1][row] = v.y;
            b_sm[kq * 4 + 2][row] = v.z; b_sm[kq * 4 + 3][row] = v.w;
        }
        __syncthreads();
#pragma unroll
        for (int kk = 0; kk < 16; kk++) {
            float4 a0 = *(const float4*)&a_sm[kk][ty * 8];
            float4 a1 = *(const float4*)&a_sm[kk][ty * 8 + 4];
            ulonglong2 b0 = *(const ulonglong2*)&b_sm[kk][tx * 8];
            ulonglong2 b1 = *(const ulonglong2*)&b_sm[kk][tx * 8 + 4];
            float av[8] = {a0.x, a0.y, a0.z, a0.w, a1.x, a1.y, a1.z, a1.w};
#pragma unroll
            for (int i = 0; i < 8; i++) {
                ull s = splat2(av[i]);
                fma2(acc[i][0], s, b0.x);
                fma2(acc[i][1], s, b0.y);
                fma2(acc[i][2], s, b1.x);
                fma2(acc[i][3], s, b1.y);
            }
        }
        __syncthreads();
    }

    const int n0 = nBase + tx * 8;
    float bj[8];
#pragma unroll
    for (int j = 0; j < 8; j++) bj[j] = bias0[n0 + j] + bias1[n0 + j];
#pragma unroll
    for (int i = 0; i < 8; i++) {
        int m = mBase + ty * 8 + i;
        float4 o0, o1;
        o0.x = lo2(acc[i][0]) + bj[0]; o0.y = hi2(acc[i][0]) + bj[1];
        o0.z = lo2(acc[i][1]) + bj[2]; o0.w = hi2(acc[i][1]) + bj[3];
        o1.x = lo2(acc[i][2]) + bj[4]; o1.y = hi2(acc[i][2]) + bj[5];
        o1.z = lo2(acc[i][3]) + bj[6]; o1.w = hi2(acc[i][3]) + bj[7];
        *(float4*)(C + (size_t)m * H_ + n0)     = o0;
        *(float4*)(C + (size_t)m * H_ + n0 + 4) = o1;
    }
}

// =====================================================================================
// Fused 2-layer recurrence: 32 clusters x 4 CTAs, 2 batch rows per cluster.
// Rank r owns k-chunk Kr=[64r,64r+64) of h1 and h2 (its epilogue outputs).
// Step t: finalize h1[t] (t<T) and h2[t-1] (t>=1); T+1 steps total.
// Matvec (thread = (d=tid>>6 dest rank, oi=tid&63), target output O=64d+oi):
//   p1[row] = Whh0[O,Kr] @ h1own[row][t-1]                      (32 fma2/row)
//   p2[row] = Wih1[O,Kr] @ h1own[row][t-1] + Whh1[O,Kr] @ h2own[row][t-2]
// Remote partials via st.async.b64 (row pair) with tx-mbar; self partials via
// STS + local mbarrier.arrive (release; waiters use acquire). Arrive count 65 =
// 1 expect_tx armer + 64 self threads. Slot t&1, parity (t>>1)&1. Phase s bytes
// (remote tx only) = 1536*[s<T] + 1536*[s>=1]. Arm phase t+2 in epilogue of t.
// Epilogue (thread = (lay=tid>>7, row=(tid>>6)&1, eoi=tid&63)): wait mbar, sum
// 4 src partials (+xp0 or +bias1), tanh, STS h*own[nb]; one __syncthreads/step.
// =====================================================================================
__global__ void __cluster_dims__(4, 1, 1) __launch_bounds__(256, 1)
rnn_fused4(const float* __restrict__ xp0,
           const float* __restrict__ Whh0, const float* __restrict__ Wih1,
           const float* __restrict__ Whh1,
           const float* __restrict__ bih1, const float* __restrict__ bhh1,
           float* __restrict__ h2last)
{
    __shared__ __align__(16) float h1own[2][2][64];      // [buf][row][oi]
    __shared__ __align__(16) float h2own[2][2][64];
    __shared__ __align__(16) float pr1[2][64][4][2];     // [buf][oi][src][row]
    __shared__ __align__(16) float pr2[2][64][4][2];
    __shared__ __align__(8)  ull mbar[2];

    const int tid = threadIdx.x;
    const unsigned r = cta_rank();                 // 0..3
    const int c = blockIdx.x >> 2;                 // cluster id 0..31 (rows 2c, 2c+1)

    // matvec mapping
    const int d  = tid >> 6;                       // dest rank
    const int oi = tid & 63;
    const int O  = 64 * d + oi;                    // target output
    const bool self = (d == (int)r);

    // epilogue mapping
    const int lay = tid >> 7, erow = (tid >> 6) & 1, eoi = tid & 63;
    const int Eo = 64 * (int)r + eoi;              // own output this thread finalizes

    // ---- weights into registers: 3 slices of Whh0/Wih1/Whh1 [O][64r .. +64) ----
    ull wA[32], wB[32], wC[32];
#pragma unroll
    for (int j = 0; j < 16; ++j) {
        ulonglong2 a = *(const ulonglong2*)(Whh0 + (size_t)O * H_ + (int)r * 64 + j * 4);
        wA[2 * j] = a.x; wA[2 * j + 1] = a.y;
        ulonglong2 b = *(const ulonglong2*)(Wih1 + (size_t)O * H_ + (int)r * 64 + j * 4);
        wB[2 * j] = b.x; wB[2 * j + 1] = b.y;
        ulonglong2 cc = *(const ulonglong2*)(Whh1 + (size_t)O * H_ + (int)r * 64 + j * 4);
        wC[2 * j] = cc.x; wC[2 * j + 1] = cc.y;
    }
    const float ebias = (lay == 1) ? (bih1[Eo] + bhh1[Eo]) : 0.f;

    // ---- init ----
    if (tid == 0) { mbar_init(su32(&mbar[0]), 65); mbar_init(su32(&mbar[1]), 65); }
    for (int i = tid; i < 2 * 2 * 64; i += 256) {
        ((float*)h1own)[i] = 0.f; ((float*)h2own)[i] = 0.f;
    }
    __syncthreads();
    if (tid == 0) {
        mbar_expect_tx(su32(&mbar[0]), 1536u);                 // phase 0: p1 only
        mbar_expect_tx(su32(&mbar[1]), 3072u);                 // phase 1: p1 + p2
    }
    cluster_sync_();                                           // all armed & visible

    const unsigned my_mbar = su32(&mbar[0]);
    // remote destination addresses (loop-invariant)
    const unsigned dpr1 = mapa_u32(su32(&pr1[0][0][0][0]), (unsigned)d) + (unsigned)(oi * 4 + (int)r) * 8u;
    const unsigned dpr2 = mapa_u32(su32(&pr2[0][0][0][0]), (unsigned)d) + (unsigned)(oi * 4 + (int)r) * 8u;
    const unsigned dmb  = mapa_u32(my_mbar, (unsigned)d);

    const size_t xrow = ((size_t)(2 * c + erow) * T_) * H_ + Eo;
    float xv = (lay == 0) ? __ldg(xp0 + xrow) : 0.f;

    for (int t = 0; t <= T_; ++t) {
        const int cb = t & 1, nb = cb ^ 1;

        // prefetch xp0 for t+1
        float xvn = 0.f;
        if (lay == 0 && t + 1 < T_) xvn = __ldg(xp0 + xrow + (size_t)(t + 1) * H_);

        const float* h1r0 = &h1own[cb][0][0];
        const float* h1r1 = &h1own[cb][1][0];

        // ---- p1 (wA @ h1own) and start p2 (wB @ h1own), both rows ----
        ull aA0 = 0, aA1 = 0, tA0 = 0, tA1 = 0;
        ull aB0 = 0, aB1 = 0, tB0 = 0, tB1 = 0;
#pragma unroll
        for (int j = 0; j < 16; ++j) {
            ulonglong2 u0 = *(const ulonglong2*)(h1r0 + j * 4);
            ulonglong2 u1 = *(const ulonglong2*)(h1r1 + j * 4);
            fma2(aA0, u0.x, wA[2 * j]); fma2(tA0, u0.y, wA[2 * j + 1]);
            fma2(aA1, u1.x, wA[2 * j]); fma2(tA1, u1.y, wA[2 * j + 1]);
            fma2(aB0, u0.x, wB[2 * j]); fma2(tB0, u0.y, wB[2 * j + 1]);
            fma2(aB1, u1.x, wB[2 * j]); fma2(tB1, u1.y, wB[2 * j + 1]);
        }
        add2(aA0, aA0, tA0); add2(aA1, aA1, tA1);
        float p1r0 = lo2(aA0) + hi2(aA0);
        float p1r1 = lo2(aA1) + hi2(aA1);

        // ship p1 early (valid for t < T)
        if (self) {
            *(float2*)&pr1[cb][oi][r][0] = make_float2(p1r0, p1r1);
        } else if (t < T_) {
            st_async_b64(dpr1 + (unsigned)cb * 2048u, pack2(p1r0, p1r1),
                         dmb + (unsigned)cb * 8u);
        }

        // ---- finish p2 (+ wC @ h2own) ----
        const float* h2r0 = &h2own[cb][0][0];
        const float* h2r1 = &h2own[cb][1][0];
#pragma unroll
        for (int j = 0; j < 16; ++j) {
            ulonglong2 g0 = *(const ulonglong2*)(h2r0 + j * 4);
            ulonglong2 g1 = *(const ulonglong2*)(h2r1 + j * 4);
            fma2(aB0, g0.x, wC[2 * j]); fma2(tB0, g0.y, wC[2 * j + 1]);
            fma2(aB1, g1.x, wC[2 * j]); fma2(tB1, g1.y, wC[2 * j + 1]);
        }
        add2(aB0, aB0, tB0); add2(aB1, aB1, tB1);
        float p2r0 = lo2(aB0) + hi2(aB0);
        float p2r1 = lo2(aB1) + hi2(aB1);

        if (self) {
            *(float2*)&pr2[cb][oi][r][0] = make_float2(p2r0, p2r1);
            mbar_arrive_local(my_mbar + (unsigned)cb * 8u);      // release own partials
        } else if (t >= 1) {
            st_async_b64(dpr2 + (unsigned)cb * 2048u, pack2(p2r0, p2r1),
                         dmb + (unsigned)cb * 8u);
        }

        // ---- epilogue ----
        mbar_wait_cluster(my_mbar + (unsigned)cb * 8u, (unsigned)(t >> 1) & 1u);
        if (tid == 0 && t + 2 <= T_) {
            unsigned bytes = (t + 2 < T_ ? 1536u : 0u) + 1536u;  // t+2 >= 1 always
            mbar_expect_tx(my_mbar + (unsigned)cb * 8u, bytes);  // arm phase t+2
        }

        if (lay == 0) {
            if (t < T_) {
                float4 A = *(const float4*)&pr1[cb][eoi][0][0];
                float4 Bv = *(const float4*)&pr1[cb][eoi][2][0];
                float s = (erow == 0) ? (A.x + A.z + Bv.x + Bv.z)
                                      : (A.y + A.w + Bv.y + Bv.w);
                h1own[nb][erow][eoi] = tanh_fast(xv + s);
            }
        } else {
            if (t >= 1) {
                float4 A = *(const float4*)&pr2[cb][eoi][0][0];
                float4 Bv = *(const float4*)&pr2[cb][eoi][2][0];
                float s = (erow == 0) ? (A.x + A.z + Bv.x + Bv.z)
                                      : (A.y + A.w + Bv.y + Bv.w);
                float h = tanh_fast(ebias + s);
                h2own[nb][erow][eoi] = h;
                if (t == T_) h2last[(size_t)(2 * c + erow) * H_ + Eo] = h;
            }
        }
        __syncthreads();                                         // h*own[nb] visible
        xv = xvn;
    }
    cluster_sync_();
}

// =====================================================================================
// Final FC: out[b] = dot(h2last[b, :], W_fc[0,:]) + b_fc[0]
// =====================================================================================
__global__ void fc_kernel(const float* __restrict__ h2l, const float* __restrict__ Wfc,
                          const float* __restrict__ bfc, float* __restrict__ out)
{
    __shared__ float red[8];
    int b = blockIdx.x, tid = threadIdx.x;
    float v = h2l[(size_t)b * H_ + tid] * Wfc[tid];
#pragma unroll
    for (int o = 16; o > 0; o >>= 1) v += __shfl_down_sync(0xffffffffu, v, o);
    if ((tid & 31) == 0) red[tid >> 5] = v;
    __syncthreads();
    if (tid < 8) {
        float s = red[tid];
#pragma unroll
        for (int o = 4; o > 0; o >>= 1) s += __shfl_down_sync(0xffu, s, o);
        if (tid == 0) out[b] = s + bfc[0];
    }
}

// =====================================================================================
extern "C" void kernel_launch(void* const* d_in, const int* in_sizes, int n_in,
                              void* d_out, int out_size)
{
    const float* x     = (const float*)d_in[0];
    const float* W_ih0 = (const float*)d_in[1];
    const float* W_hh0 = (const float*)d_in[2];
    const float* b_ih0 = (const float*)d_in[3];
    const float* b_hh0 = (const float*)d_in[4];
    const float* W_ih1 = (const float*)d_in[5];
    const float* W_hh1 = (const float*)d_in[6];
    const float* b_ih1 = (const float*)d_in[7];
    const float* b_hh1 = (const float*)d_in[8];
    const float* W_fc  = (const float*)d_in[9];
    const float* b_fc  = (const float*)d_in[10];
    float* out = (float*)d_out;

    float *xp, *h2l;
    cudaGetSymbolAddress((void**)&xp, g_xp);
    cudaGetSymbolAddress((void**)&h2l, g_h2last);

    dim3 ggemm(M_ / 128, H_ / 128);

    // Phase A: xp0 = x @ W_ih0^T + b_ih0 + b_hh0
    gemm_bias_kernel<<<ggemm, 256>>>(x, W_ih0, b_ih0, b_hh0, xp, IN_);
    // Phase B: fused layer0+layer1 recurrence (T+1 steps, 32 clusters x 4 CTAs)
    rnn_fused4<<<128, 256>>>(xp, W_hh0, W_ih1, W_hh1, b_ih1, b_hh1, h2l);
    // Phase C: final projection
    fc_kernel<<<B_, H_>>>(h2l, W_fc, b_fc, out);
}